// round 9
// baseline (speedup 1.0000x reference)
#include <cuda_runtime.h>
#include <math.h>
#include <stdint.h>

#define GN 8192
#define GF 512

// ---------------- device scratch (allocation-free) ----------------
__device__ __align__(16) float g_h [GN * GF];   // h fp32 [j][f]
__device__ __align__(16) float g_ht[GF * GN];   // h^T tf32-rounded [f][j]
__device__ float g_s1[GN], g_s2[GN];
__device__ float g_E1[GN], g_F1[GN], g_E2[GN], g_F2[GN];

// ---------------------------------------------------------------------------
// Kernel 1: h = inp @ W1 + b1 (fp32 SGEMM) + fused tf32 transpose epilogue
// ---------------------------------------------------------------------------
__global__ __launch_bounds__(256) void gemm_h_kernel(
    const float* __restrict__ A,
    const float* __restrict__ B,
    const float* __restrict__ bias)
{
    __shared__ float As[8][132];
    __shared__ float Bs[8][128];

    const int tid = threadIdx.x;
    const int bx = blockIdx.x;
    const int by = blockIdx.y;
    const int tx = tid & 15;
    const int ty = tid >> 4;

    float acc[8][8];
#pragma unroll
    for (int i = 0; i < 8; i++)
#pragma unroll
        for (int j = 0; j < 8; j++) acc[i][j] = 0.f;

    const int a_r = tid >> 1;
    const int a_k = (tid & 1) * 4;
    const int b_k = tid >> 5;
    const int b_n = (tid & 31) * 4;

    const float* Aptr = A + (by * 128 + a_r) * GF + a_k;
    const float* Bptr = B + b_k * GF + bx * 128 + b_n;

    for (int k0 = 0; k0 < GF; k0 += 8) {
        float4 av = *(const float4*)(Aptr + k0);
        float4 bv = *(const float4*)(Bptr + k0 * GF);
        __syncthreads();
        As[a_k + 0][a_r] = av.x;
        As[a_k + 1][a_r] = av.y;
        As[a_k + 2][a_r] = av.z;
        As[a_k + 3][a_r] = av.w;
        *(float4*)&Bs[b_k][b_n] = bv;
        __syncthreads();

#pragma unroll
        for (int kk = 0; kk < 8; kk++) {
            float af[8], bf[8];
#pragma unroll
            for (int i = 0; i < 8; i++) af[i] = As[kk][ty * 8 + i];
#pragma unroll
            for (int j = 0; j < 8; j++) bf[j] = Bs[kk][tx * 8 + j];
#pragma unroll
            for (int i = 0; i < 8; i++)
#pragma unroll
                for (int j = 0; j < 8; j++) acc[i][j] += af[i] * bf[j];
        }
    }

    const int row0 = by * 128 + ty * 8;
    const int col0 = bx * 128 + tx * 8;
    float4 bb0 = *(const float4*)(bias + col0);
    float4 bb1 = *(const float4*)(bias + col0 + 4);
#pragma unroll
    for (int i = 0; i < 8; i++) {
        acc[i][0] += bb0.x; acc[i][1] += bb0.y;
        acc[i][2] += bb0.z; acc[i][3] += bb0.w;
        acc[i][4] += bb1.x; acc[i][5] += bb1.y;
        acc[i][6] += bb1.z; acc[i][7] += bb1.w;
    }

#pragma unroll
    for (int i = 0; i < 8; i++) {
        *(float4*)&g_h[(row0 + i) * GF + col0] =
            make_float4(acc[i][0], acc[i][1], acc[i][2], acc[i][3]);
        *(float4*)&g_h[(row0 + i) * GF + col0 + 4] =
            make_float4(acc[i][4], acc[i][5], acc[i][6], acc[i][7]);
    }

#pragma unroll
    for (int j = 0; j < 8; j++) {
        float t[8];
#pragma unroll
        for (int i = 0; i < 8; i++) {
            unsigned u;
            asm("cvt.rna.tf32.f32 %0, %1;" : "=r"(u) : "f"(acc[i][j]));
            t[i] = __uint_as_float(u);
        }
        float* dst = g_ht + (size_t)(col0 + j) * GN + row0;
        *(float4*)dst       = make_float4(t[0], t[1], t[2], t[3]);
        *(float4*)(dst + 4) = make_float4(t[4], t[5], t[6], t[7]);
    }
}

// ---------------------------------------------------------------------------
// Kernel 2: s1/s2 dots
// ---------------------------------------------------------------------------
__global__ __launch_bounds__(128) void s1s2_kernel(
    const float* __restrict__ a1, const float* __restrict__ a2)
{
    const int row = blockIdx.x;
    const int tid = threadIdx.x;

    float4 hv = *(const float4*)(g_h + row * GF + tid * 4);
    float4 v1 = *(const float4*)(a1 + tid * 4);
    float4 v2 = *(const float4*)(a2 + tid * 4);
    float p1 = hv.x * v1.x + hv.y * v1.y + hv.z * v1.z + hv.w * v1.w;
    float p2 = hv.x * v2.x + hv.y * v2.y + hv.z * v2.z + hv.w * v2.w;

#pragma unroll
    for (int o = 16; o > 0; o >>= 1) {
        p1 += __shfl_down_sync(0xffffffffu, p1, o);
        p2 += __shfl_down_sync(0xffffffffu, p2, o);
    }
    __shared__ float r1[4], r2[4];
    const int lane = tid & 31, w = tid >> 5;
    if (lane == 0) { r1[w] = p1; r2[w] = p2; }
    __syncthreads();
    if (tid == 0) {
        g_s1[row] = r1[0] + r1[1] + r1[2] + r1[3];
        g_s2[row] = r2[0] + r2[1] + r2[2] + r2[3];
    }
}

// ---------------------------------------------------------------------------
// Kernel 3: factorized exp precompute
// ---------------------------------------------------------------------------
__global__ __launch_bounds__(256) void prep_kernel(const float* __restrict__ b2p)
{
    const int i = blockIdx.x * 256 + threadIdx.x;
    const float b2 = *b2p;
    const float x1 = g_s1[i] + b2;
    const float x2 = g_s2[i];
    g_E1[i] = __expf(x1);
    g_F1[i] = __expf(0.2f * x1);
    g_E2[i] = __expf(x2);
    g_F2[i] = __expf(0.2f * x2);
}

// ---------------------------------------------------------------------------
// Kernel 4: fused attention, tf32 mma.sync, F-split.
// CTA = (32 rows) x (256 of 512 cols). grid = 256 rowblocks x 2 fhalves = 512.
// Per 32-wide j-tile: A = P frags (fragment-ready float4 layout, built by the
// exact thread that later... by index identity), B = hT half-slab in smem.
// Double-buffered, ONE __syncthreads per tile. Epilogue writes final output.
// ---------------------------------------------------------------------------
#define AM 32
#define FH 256
#define AK 32
#define NTT (GN / AK)
#define HTS 36
#define HB_BYTES (FH * HTS * 4)        // 36864
#define PF_BYTES (256 * 16)            // 4096
#define SMEM_ATTN (2 * HB_BYTES + 2 * PF_BYTES + 128)   // 82048

__device__ __forceinline__ void mma8(float* c, float4 a, float b0, float b1)
{
    asm volatile(
        "mma.sync.aligned.m16n8k8.row.col.f32.tf32.tf32.f32 "
        "{%0,%1,%2,%3}, {%4,%5,%6,%7}, {%8,%9}, {%0,%1,%2,%3};\n"
        : "+f"(c[0]), "+f"(c[1]), "+f"(c[2]), "+f"(c[3])
        : "r"(__float_as_uint(a.x)), "r"(__float_as_uint(a.y)),
          "r"(__float_as_uint(a.z)), "r"(__float_as_uint(a.w)),
          "r"(__float_as_uint(b0)), "r"(__float_as_uint(b1)));
}

__device__ __forceinline__ float tf32r(float x)
{
    unsigned u;
    asm("cvt.rna.tf32.f32 %0, %1;" : "=r"(u) : "f"(x));
    return __uint_as_float(u);
}

__global__ __launch_bounds__(256, 2) void gat_attn2(
    const int* __restrict__ adj, float* __restrict__ out)
{
    extern __shared__ char smraw[];
    float*  hb0 = (float*)smraw;
    float*  hb1 = (float*)(smraw + HB_BYTES);
    float4* PF0 = (float4*)(smraw + 2 * HB_BYTES);
    float4* PF1 = (float4*)(smraw + 2 * HB_BYTES + PF_BYTES);
    float*  ls  = (float*)(smraw + 2 * HB_BYTES + 2 * PF_BYTES);

    const int tid  = threadIdx.x;
    const int w    = tid >> 5;
    const int lane = tid & 31;
    const int gid  = lane >> 2;          // 0..7
    const int tig  = lane & 3;           // 0..3

    const int i0 = (blockIdx.x >> 1) * AM;
    const int fh = blockIdx.x & 1;

    if (tid < AM) ls[tid] = 0.f;

    // producer identity: tid = ((pks*2+pmt)*8+pgid)*4+ptig  == consumer A-frag index
    const int ptig = tid & 3;
    const int pgid = (tid >> 2) & 7;
    const int pmt  = (tid >> 5) & 1;
    const int pks  = tid >> 6;
    const int r0 = pmt * 16 + pgid, r1 = r0 + 8;
    const int c0 = pks * 8 + ptig,  c1 = c0 + 4;

    const float e1a = g_E1[i0 + r0], e1b = g_E1[i0 + r1];
    const float f1a = g_F1[i0 + r0], f1b = g_F1[i0 + r1];
    const int* arow0 = adj + (size_t)(i0 + r0) * GN;
    const int* arow1 = adj + (size_t)(i0 + r1) * GN;

    float lacc0 = 0.f, lacc1 = 0.f;
    float acc[2][4][4];
#pragma unroll
    for (int mt = 0; mt < 2; mt++)
#pragma unroll
        for (int nt = 0; nt < 4; nt++)
#pragma unroll
            for (int q = 0; q < 4; q++) acc[mt][nt][q] = 0.f;

    // cp.async mapping: f-row = (tid>>3) + 32*s, 16B chunk (tid&7)
    const int cf = tid >> 3, cp4 = (tid & 7) * 4;
    const float* csrc = g_ht + (size_t)(fh * FH + cf) * GN + cp4;
    const uint32_t cd0 = (uint32_t)__cvta_generic_to_shared(hb0)
                       + (uint32_t)(cf * HTS + cp4) * 4u;
    const uint32_t cd1 = (uint32_t)__cvta_generic_to_shared(hb1)
                       + (uint32_t)(cf * HTS + cp4) * 4u;

    int a00, a01, a10, a11;
    float E2a, E2b, F2a, F2b;

#define PREFETCH(J) do {                                                   \
    a00 = __ldg(arow0 + (J) + c0); a01 = __ldg(arow0 + (J) + c1);          \
    a10 = __ldg(arow1 + (J) + c0); a11 = __ldg(arow1 + (J) + c1);          \
    E2a = __ldg(&g_E2[(J) + c0]);  E2b = __ldg(&g_E2[(J) + c1]);           \
    F2a = __ldg(&g_F2[(J) + c0]);  F2b = __ldg(&g_F2[(J) + c1]);           \
} while (0)

#define CPASYNC(J, DST) do {                                               \
    _Pragma("unroll")                                                      \
    for (int s = 0; s < 8; s++) {                                          \
        asm volatile("cp.async.cg.shared.global [%0], [%1], 16;"           \
                     :: "r"((DST) + (uint32_t)(s * 32 * HTS * 4)),         \
                        "l"(csrc + (size_t)s * 32 * GN + (J)));            \
    }                                                                      \
    asm volatile("cp.async.commit_group;");                                \
} while (0)

#define PRODUCE(DST) do {                                                  \
    float u00 = e1a * E2a, v00 = f1a * F2a;                                \
    float u01 = e1a * E2b, v01 = f1a * F2b;                                \
    float u10 = e1b * E2a, v10 = f1b * F2a;                                \
    float u11 = e1b * E2b, v11 = f1b * F2b;                                \
    float p00 = (a00 > 0) ? (u00 > 1.f ? u00 : v00) : 0.f;                 \
    float p01 = (a01 > 0) ? (u01 > 1.f ? u01 : v01) : 0.f;                 \
    float p10 = (a10 > 0) ? (u10 > 1.f ? u10 : v10) : 0.f;                 \
    float p11 = (a11 > 0) ? (u11 > 1.f ? u11 : v11) : 0.f;                 \
    p00 = tf32r(p00); p01 = tf32r(p01); p10 = tf32r(p10); p11 = tf32r(p11);\
    lacc0 += p00 + p01; lacc1 += p10 + p11;                                \
    (DST)[tid] = make_float4(p00, p10, p01, p11);                          \
} while (0)

    // prologue: tile 0 in flight + P0 produced, regs for tile 1 prefetched
    PREFETCH(0);
    CPASYNC(0, cd0);
    PRODUCE(PF0);
    PREFETCH(AK);

    for (int t = 0; t < NTT; t++) {
        const int j0 = t * AK;

        asm volatile("cp.async.wait_group 0;" ::: "memory");
        __syncthreads();   // tile t visible everywhere; MMA(t-1) fully done

        if (t + 1 < NTT) {
            CPASYNC(j0 + AK, (t & 1) ? cd0 : cd1);
            PRODUCE((t & 1) ? PF0 : PF1);
            if (t + 2 < NTT) PREFETCH(j0 + 2 * AK);
        }

        const float4* pf = (t & 1) ? PF1 : PF0;
        const float*  hb = (t & 1) ? hb1 : hb0;

        float4 af[8];
#pragma unroll
        for (int k8 = 0; k8 < 8; k8++) af[k8] = pf[k8 * 32 + lane];

#pragma unroll
        for (int nt = 0; nt < 4; nt++) {
            const float* bp = hb + (w * 32 + nt * 8 + gid) * HTS + tig;
#pragma unroll
            for (int ks = 0; ks < 4; ks++) {
                const float b0 = bp[ks * 8];
                const float b1 = bp[ks * 8 + 4];
                mma8(acc[0][nt], af[ks * 2 + 0], b0, b1);
                mma8(acc[1][nt], af[ks * 2 + 1], b0, b1);
            }
        }
    }

    // row sums (16 scattered partials per row -> smem atomics, once per CTA)
    atomicAdd(&ls[r0], lacc0);
    atomicAdd(&ls[r1], lacc1);
    __syncthreads();

    // epilogue: normalize + elu + final store (no combine pass needed)
#pragma unroll
    for (int mt = 0; mt < 2; mt++) {
        const int rA = mt * 16 + gid;
        const int rB = rA + 8;
        const float invA = 1.0f / ls[rA];
        const float invB = 1.0f / ls[rB];
#pragma unroll
        for (int nt = 0; nt < 4; nt++) {
            const int col = fh * FH + w * 32 + nt * 8 + tig * 2;
            float o0 = acc[mt][nt][0] * invA;
            float o1 = acc[mt][nt][1] * invA;
            float o2 = acc[mt][nt][2] * invB;
            float o3 = acc[mt][nt][3] * invB;
            o0 = o0 > 0.f ? o0 : (__expf(o0) - 1.f);
            o1 = o1 > 0.f ? o1 : (__expf(o1) - 1.f);
            o2 = o2 > 0.f ? o2 : (__expf(o2) - 1.f);
            o3 = o3 > 0.f ? o3 : (__expf(o3) - 1.f);
            *(float2*)&out[(size_t)(i0 + rA) * GF + col] = make_float2(o0, o1);
            *(float2*)&out[(size_t)(i0 + rB) * GF + col] = make_float2(o2, o3);
        }
    }
}

// ---------------------------------------------------------------------------
extern "C" void kernel_launch(void* const* d_in, const int* in_sizes, int n_in,
                              void* d_out, int out_size)
{
    const float* inp = (const float*)d_in[0];
    const int*   adj = (const int*)d_in[1];
    const float* W1  = (const float*)d_in[2];
    const float* b1  = (const float*)d_in[3];
    const float* a1  = (const float*)d_in[4];
    const float* a2  = (const float*)d_in[5];
    const float* b2  = (const float*)d_in[6];
    float* out = (float*)d_out;

    (void)in_sizes; (void)n_in; (void)out_size;

    cudaFuncSetAttribute(gat_attn2,
                         cudaFuncAttributeMaxDynamicSharedMemorySize, SMEM_ATTN);

    gemm_h_kernel<<<dim3(GF / 128, GN / 128), 256>>>(inp, W1, b1);
    s1s2_kernel<<<GN, 128>>>(a1, a2);
    prep_kernel<<<GN / 256, 256>>>(b2);
    gat_attn2<<<(GN / AM) * 2, 256, SMEM_ATTN>>>(adj, out);
}

// round 10
// speedup vs baseline: 1.0615x; 1.0615x over previous
#include <cuda_runtime.h>
#include <math.h>
#include <stdint.h>

#define GN 8192
#define GF 512

// ---------------- device scratch (allocation-free) ----------------
__device__ __align__(16) float g_h [GN * GF];   // h fp32 [j][f]
__device__ __align__(16) float g_ht[GF * GN];   // h^T tf32-rounded [f][j]
__device__ float g_s1[GN], g_s2[GN];
__device__ float g_E1[GN], g_F1[GN], g_E2[GN], g_F2[GN];

// ---------------------------------------------------------------------------
// Kernel 1: h = inp @ W1 + b1 (fp32 SGEMM) + fused tf32 transpose epilogue
// ---------------------------------------------------------------------------
__global__ __launch_bounds__(256) void gemm_h_kernel(
    const float* __restrict__ A,
    const float* __restrict__ B,
    const float* __restrict__ bias)
{
    __shared__ float As[8][132];
    __shared__ float Bs[8][128];

    const int tid = threadIdx.x;
    const int bx = blockIdx.x;
    const int by = blockIdx.y;
    const int tx = tid & 15;
    const int ty = tid >> 4;

    float acc[8][8];
#pragma unroll
    for (int i = 0; i < 8; i++)
#pragma unroll
        for (int j = 0; j < 8; j++) acc[i][j] = 0.f;

    const int a_r = tid >> 1;
    const int a_k = (tid & 1) * 4;
    const int b_k = tid >> 5;
    const int b_n = (tid & 31) * 4;

    const float* Aptr = A + (by * 128 + a_r) * GF + a_k;
    const float* Bptr = B + b_k * GF + bx * 128 + b_n;

    for (int k0 = 0; k0 < GF; k0 += 8) {
        float4 av = *(const float4*)(Aptr + k0);
        float4 bv = *(const float4*)(Bptr + k0 * GF);
        __syncthreads();
        As[a_k + 0][a_r] = av.x;
        As[a_k + 1][a_r] = av.y;
        As[a_k + 2][a_r] = av.z;
        As[a_k + 3][a_r] = av.w;
        *(float4*)&Bs[b_k][b_n] = bv;
        __syncthreads();

#pragma unroll
        for (int kk = 0; kk < 8; kk++) {
            float af[8], bf[8];
#pragma unroll
            for (int i = 0; i < 8; i++) af[i] = As[kk][ty * 8 + i];
#pragma unroll
            for (int j = 0; j < 8; j++) bf[j] = Bs[kk][tx * 8 + j];
#pragma unroll
            for (int i = 0; i < 8; i++)
#pragma unroll
                for (int j = 0; j < 8; j++) acc[i][j] += af[i] * bf[j];
        }
    }

    const int row0 = by * 128 + ty * 8;
    const int col0 = bx * 128 + tx * 8;
    float4 bb0 = *(const float4*)(bias + col0);
    float4 bb1 = *(const float4*)(bias + col0 + 4);
#pragma unroll
    for (int i = 0; i < 8; i++) {
        acc[i][0] += bb0.x; acc[i][1] += bb0.y;
        acc[i][2] += bb0.z; acc[i][3] += bb0.w;
        acc[i][4] += bb1.x; acc[i][5] += bb1.y;
        acc[i][6] += bb1.z; acc[i][7] += bb1.w;
    }

#pragma unroll
    for (int i = 0; i < 8; i++) {
        *(float4*)&g_h[(row0 + i) * GF + col0] =
            make_float4(acc[i][0], acc[i][1], acc[i][2], acc[i][3]);
        *(float4*)&g_h[(row0 + i) * GF + col0 + 4] =
            make_float4(acc[i][4], acc[i][5], acc[i][6], acc[i][7]);
    }

#pragma unroll
    for (int j = 0; j < 8; j++) {
        float t[8];
#pragma unroll
        for (int i = 0; i < 8; i++) {
            unsigned u;
            asm("cvt.rna.tf32.f32 %0, %1;" : "=r"(u) : "f"(acc[i][j]));
            t[i] = __uint_as_float(u);
        }
        float* dst = g_ht + (size_t)(col0 + j) * GN + row0;
        *(float4*)dst       = make_float4(t[0], t[1], t[2], t[3]);
        *(float4*)(dst + 4) = make_float4(t[4], t[5], t[6], t[7]);
    }
}

// ---------------------------------------------------------------------------
// Kernel 2: s1/s2 dots
// ---------------------------------------------------------------------------
__global__ __launch_bounds__(128) void s1s2_kernel(
    const float* __restrict__ a1, const float* __restrict__ a2)
{
    const int row = blockIdx.x;
    const int tid = threadIdx.x;

    float4 hv = *(const float4*)(g_h + row * GF + tid * 4);
    float4 v1 = *(const float4*)(a1 + tid * 4);
    float4 v2 = *(const float4*)(a2 + tid * 4);
    float p1 = hv.x * v1.x + hv.y * v1.y + hv.z * v1.z + hv.w * v1.w;
    float p2 = hv.x * v2.x + hv.y * v2.y + hv.z * v2.z + hv.w * v2.w;

#pragma unroll
    for (int o = 16; o > 0; o >>= 1) {
        p1 += __shfl_down_sync(0xffffffffu, p1, o);
        p2 += __shfl_down_sync(0xffffffffu, p2, o);
    }
    __shared__ float r1[4], r2[4];
    const int lane = tid & 31, w = tid >> 5;
    if (lane == 0) { r1[w] = p1; r2[w] = p2; }
    __syncthreads();
    if (tid == 0) {
        g_s1[row] = r1[0] + r1[1] + r1[2] + r1[3];
        g_s2[row] = r2[0] + r2[1] + r2[2] + r2[3];
    }
}

// ---------------------------------------------------------------------------
// Kernel 3: factorized exp precompute
// ---------------------------------------------------------------------------
__global__ __launch_bounds__(256) void prep_kernel(const float* __restrict__ b2p)
{
    const int i = blockIdx.x * 256 + threadIdx.x;
    const float b2 = *b2p;
    const float x1 = g_s1[i] + b2;
    const float x2 = g_s2[i];
    g_E1[i] = __expf(x1);
    g_F1[i] = __expf(0.2f * x1);
    g_E2[i] = __expf(x2);
    g_F2[i] = __expf(0.2f * x2);
}

// ---------------------------------------------------------------------------
// Kernel 4: fused attention. AM=32 rows/CTA, full F=512, 8 warps, 2 CTA/SM.
// AK=16 j-tiles. B slabs are PER-WARP (warp w reads only hT rows w*64..+64):
// each warp cp.asyncs its own slab, guarded by its own wait_group -> B needs
// NO block barrier. P is quad-buffered fragment-ready float4 produced 2 tiles
// ahead -> exactly ONE bar.sync per tile.
// ---------------------------------------------------------------------------
#define AM 32
#define AK 16
#define NTT (GN / AK)                    // 512
#define BST 20                           // padded slab stride (floats)
#define SLAB_F (64 * BST)                // floats per warp-slab   (1280)
#define BUF_F  (8 * SLAB_F)              // floats per B buffer   (10240)
#define PF_OFF (2 * BUF_F * 4)           // 81920 B
#define LS_OFF (PF_OFF + 4 * 128 * 16)   // 81920 + 8192 = 90112
#define SMEM_ATTN (LS_OFF + 128)         // 90240 B

__device__ __forceinline__ void mma8(float* c, float4 a, float b0, float b1)
{
    asm volatile(
        "mma.sync.aligned.m16n8k8.row.col.f32.tf32.tf32.f32 "
        "{%0,%1,%2,%3}, {%4,%5,%6,%7}, {%8,%9}, {%0,%1,%2,%3};\n"
        : "+f"(c[0]), "+f"(c[1]), "+f"(c[2]), "+f"(c[3])
        : "r"(__float_as_uint(a.x)), "r"(__float_as_uint(a.y)),
          "r"(__float_as_uint(a.z)), "r"(__float_as_uint(a.w)),
          "r"(__float_as_uint(b0)), "r"(__float_as_uint(b1)));
}

__device__ __forceinline__ float tf32r(float x)
{
    unsigned u;
    asm("cvt.rna.tf32.f32 %0, %1;" : "=r"(u) : "f"(x));
    return __uint_as_float(u);
}

__global__ __launch_bounds__(256, 2) void gat_attn3(
    const int* __restrict__ adj, float* __restrict__ out)
{
    extern __shared__ char smraw[];
    float*  HB = (float*)smraw;                    // B slabs, 2 bufs x 8 warps
    float4* PF = (float4*)(smraw + PF_OFF);        // 4 bufs x 128 float4
    float*  ls = (float*)(smraw + LS_OFF);

    const int tid  = threadIdx.x;
    const int w    = tid >> 5;
    const int lane = tid & 31;
    const int gid  = lane >> 2;
    const int tig  = lane & 3;
    const int i0   = blockIdx.x * AM;

    if (tid < AM) ls[tid] = 0.f;

    float acc[2][8][4];
#pragma unroll
    for (int mt = 0; mt < 2; mt++)
#pragma unroll
        for (int nt = 0; nt < 8; nt++)
#pragma unroll
            for (int q = 0; q < 4; q++) acc[mt][nt][q] = 0.f;

    // ---- producer identity (threads 0..127): PF index == tid
    const int ptig = tid & 3;
    const int pgid = (tid >> 2) & 7;
    const int pmt  = (tid >> 5) & 1;
    const int pks  = (tid >> 6) & 1;
    const int r0 = pmt * 16 + pgid, r1 = r0 + 8;
    const int c0 = pks * 8 + ptig,  c1 = c0 + 4;
    const bool isprod = (tid < 128);

    float e1a = 0.f, e1b = 0.f, f1a = 0.f, f1b = 0.f;
    const int* arow0 = adj + (size_t)(i0 + r0) * GN;
    const int* arow1 = adj + (size_t)(i0 + r1) * GN;
    if (isprod) {
        e1a = g_E1[i0 + r0]; e1b = g_E1[i0 + r1];
        f1a = g_F1[i0 + r0]; f1b = g_F1[i0 + r1];
    }
    float lacc0 = 0.f, lacc1 = 0.f;
    int a00 = 0, a01 = 0, a10 = 0, a11 = 0;
    float E2a = 0.f, E2b = 0.f, F2a = 0.f, F2b = 0.f;

    // ---- per-warp cp.async mapping (own slab): 8 passes of 16B/thread
    const int bq  = lane >> 2;                     // local f-row 0..7 (+8s)
    const int bc4 = lane & 3;                      // 16B chunk in 64B row
    const float* bsrc = g_ht + (size_t)(w * 64 + bq) * GN + bc4 * 4;
    const uint32_t bdst = (uint32_t)__cvta_generic_to_shared(HB)
                        + (uint32_t)(w * SLAB_F + bq * BST + bc4 * 4) * 4u;

#define PREFETCH(J) do {                                                   \
    if (isprod) {                                                          \
        a00 = __ldg(arow0 + (J) + c0); a01 = __ldg(arow0 + (J) + c1);      \
        a10 = __ldg(arow1 + (J) + c0); a11 = __ldg(arow1 + (J) + c1);      \
        E2a = __ldg(&g_E2[(J) + c0]);  E2b = __ldg(&g_E2[(J) + c1]);       \
        F2a = __ldg(&g_F2[(J) + c0]);  F2b = __ldg(&g_F2[(J) + c1]);       \
    }                                                                      \
} while (0)

#define PRODUCE(PB) do {                                                   \
    if (isprod) {                                                          \
        float u00 = e1a * E2a, v00 = f1a * F2a;                            \
        float u01 = e1a * E2b, v01 = f1a * F2b;                            \
        float u10 = e1b * E2a, v10 = f1b * F2a;                            \
        float u11 = e1b * E2b, v11 = f1b * F2b;                            \
        float p00 = (a00 > 0) ? (u00 > 1.f ? u00 : v00) : 0.f;             \
        float p01 = (a01 > 0) ? (u01 > 1.f ? u01 : v01) : 0.f;             \
        float p10 = (a10 > 0) ? (u10 > 1.f ? u10 : v10) : 0.f;             \
        float p11 = (a11 > 0) ? (u11 > 1.f ? u11 : v11) : 0.f;             \
        p00 = tf32r(p00); p01 = tf32r(p01);                                \
        p10 = tf32r(p10); p11 = tf32r(p11);                                \
        lacc0 += p00 + p01; lacc1 += p10 + p11;                            \
        PF[(PB) * 128 + tid] = make_float4(p00, p10, p01, p11);            \
    }                                                                      \
} while (0)

#define CPASYNC(J, BUF) do {                                               \
    const uint32_t _d = bdst + (uint32_t)(BUF) * (BUF_F * 4);              \
    const float* _s = bsrc + (J);                                          \
    _Pragma("unroll")                                                      \
    for (int s = 0; s < 8; s++) {                                          \
        asm volatile("cp.async.ca.shared.global [%0], [%1], 16;"           \
                     :: "r"(_d + (uint32_t)(s * 8 * BST * 4)),             \
                        "l"(_s + (size_t)s * 8 * GN));                     \
    }                                                                      \
    asm volatile("cp.async.commit_group;");                                \
} while (0)

    // ---- prologue: PF(0), PF(1) ready; regs for tile 2; B groups 0,1 in flight
    PREFETCH(0);
    PRODUCE(0);
    PREFETCH(AK);
    PRODUCE(1);
    PREFETCH(2 * AK);
    CPASYNC(0, 0);
    CPASYNC(AK, 1);

    for (int t = 0; t < NTT; t++) {
        if (t + 2 < NTT)
            asm volatile("cp.async.wait_group 1;" ::: "memory");
        else
            asm volatile("cp.async.wait_group 0;" ::: "memory");
        __syncthreads();   // PF[t&3] visible; own slab (t&1) arrived

        // ---- MMA(t)
        {
            float4 af[4];
#pragma unroll
            for (int f = 0; f < 4; f++) af[f] = PF[(t & 3) * 128 + f * 32 + lane];

            const float* slab = HB + (t & 1) * BUF_F + w * SLAB_F;
#pragma unroll
            for (int nt = 0; nt < 8; nt++) {
                const float* bp = slab + (nt * 8 + gid) * BST + tig;
#pragma unroll
                for (int ks = 0; ks < 2; ks++) {
                    const float b0 = bp[ks * 8];
                    const float b1 = bp[ks * 8 + 4];
                    mma8(acc[0][nt], af[ks * 2 + 0], b0, b1);
                    mma8(acc[1][nt], af[ks * 2 + 1], b0, b1);
                }
            }
        }

        // ---- stage tile t+2 (overlaps with MMA drain; no extra barrier)
        if (t + 2 < NTT) {
            PRODUCE((t + 2) & 3);
            CPASYNC((t + 2) * AK, (t & 1));
            if (t + 3 < NTT) PREFETCH((t + 3) * AK);
        }
    }

    // ---- row sums
    if (isprod) {
        atomicAdd(&ls[r0], lacc0);
        atomicAdd(&ls[r1], lacc1);
    }
    __syncthreads();

    // ---- epilogue: normalize + elu + store
#pragma unroll
    for (int mt = 0; mt < 2; mt++) {
        const int rA = mt * 16 + gid;
        const int rB = rA + 8;
        const float invA = 1.0f / ls[rA];
        const float invB = 1.0f / ls[rB];
#pragma unroll
        for (int nt = 0; nt < 8; nt++) {
            const int col = w * 64 + nt * 8 + tig * 2;
            float o0 = acc[mt][nt][0] * invA;
            float o1 = acc[mt][nt][1] * invA;
            float o2 = acc[mt][nt][2] * invB;
            float o3 = acc[mt][nt][3] * invB;
            o0 = o0 > 0.f ? o0 : (__expf(o0) - 1.f);
            o1 = o1 > 0.f ? o1 : (__expf(o1) - 1.f);
            o2 = o2 > 0.f ? o2 : (__expf(o2) - 1.f);
            o3 = o3 > 0.f ? o3 : (__expf(o3) - 1.f);
            *(float2*)&out[(size_t)(i0 + rA) * GF + col] = make_float2(o0, o1);
            *(float2*)&out[(size_t)(i0 + rB) * GF + col] = make_float2(o2, o3);
        }
    }
}

// ---------------------------------------------------------------------------
extern "C" void kernel_launch(void* const* d_in, const int* in_sizes, int n_in,
                              void* d_out, int out_size)
{
    const float* inp = (const float*)d_in[0];
    const int*   adj = (const int*)d_in[1];
    const float* W1  = (const float*)d_in[2];
    const float* b1  = (const float*)d_in[3];
    const float* a1  = (const float*)d_in[4];
    const float* a2  = (const float*)d_in[5];
    const float* b2  = (const float*)d_in[6];
    float* out = (float*)d_out;

    (void)in_sizes; (void)n_in; (void)out_size;

    cudaFuncSetAttribute(gat_attn3,
                         cudaFuncAttributeMaxDynamicSharedMemorySize, SMEM_ATTN);

    gemm_h_kernel<<<dim3(GF / 128, GN / 128), 256>>>(inp, W1, b1);
    s1s2_kernel<<<GN, 128>>>(a1, a2);
    prep_kernel<<<GN / 256, 256>>>(b2);
    gat_attn3<<<GN / AM, 256, SMEM_ATTN>>>(adj, out);
}

// round 11
// speedup vs baseline: 1.4303x; 1.3474x over previous
#include <cuda_runtime.h>
#include <math.h>
#include <stdint.h>

#define GN 8192
#define GF 512

// ---------------- device scratch (allocation-free) ----------------
__device__ __align__(16) float g_h  [GN * GF];  // h fp32 [j][f]
__device__ __align__(16) float g_htf[GF * GN];  // h^T tf32, FRAGMENT-PACKED
__device__ float g_s1[GN], g_s2[GN];
__device__ float g_E1[GN], g_F1[GN], g_E2[GN], g_F2[GN];

// ---------------------------------------------------------------------------
// Kernel 1: h = inp @ W1 + b1 (fp32 SGEMM 128x128x8)
// ---------------------------------------------------------------------------
__global__ __launch_bounds__(256) void gemm_h_kernel(
    const float* __restrict__ A,
    const float* __restrict__ B,
    const float* __restrict__ bias)
{
    __shared__ float As[8][132];
    __shared__ float Bs[8][128];

    const int tid = threadIdx.x;
    const int bx = blockIdx.x;
    const int by = blockIdx.y;
    const int tx = tid & 15;
    const int ty = tid >> 4;

    float acc[8][8];
#pragma unroll
    for (int i = 0; i < 8; i++)
#pragma unroll
        for (int j = 0; j < 8; j++) acc[i][j] = 0.f;

    const int a_r = tid >> 1;
    const int a_k = (tid & 1) * 4;
    const int b_k = tid >> 5;
    const int b_n = (tid & 31) * 4;

    const float* Aptr = A + (by * 128 + a_r) * GF + a_k;
    const float* Bptr = B + b_k * GF + bx * 128 + b_n;

    for (int k0 = 0; k0 < GF; k0 += 8) {
        float4 av = *(const float4*)(Aptr + k0);
        float4 bv = *(const float4*)(Bptr + k0 * GF);
        __syncthreads();
        As[a_k + 0][a_r] = av.x;
        As[a_k + 1][a_r] = av.y;
        As[a_k + 2][a_r] = av.z;
        As[a_k + 3][a_r] = av.w;
        *(float4*)&Bs[b_k][b_n] = bv;
        __syncthreads();

#pragma unroll
        for (int kk = 0; kk < 8; kk++) {
            float af[8], bf[8];
#pragma unroll
            for (int i = 0; i < 8; i++) af[i] = As[kk][ty * 8 + i];
#pragma unroll
            for (int j = 0; j < 8; j++) bf[j] = Bs[kk][tx * 8 + j];
#pragma unroll
            for (int i = 0; i < 8; i++)
#pragma unroll
                for (int j = 0; j < 8; j++) acc[i][j] += af[i] * bf[j];
        }
    }

    const int row0 = by * 128 + ty * 8;
    const int col0 = bx * 128 + tx * 8;
    float4 bb0 = *(const float4*)(bias + col0);
    float4 bb1 = *(const float4*)(bias + col0 + 4);
#pragma unroll
    for (int i = 0; i < 8; i++) {
        float4 v0, v1;
        v0.x = acc[i][0] + bb0.x; v0.y = acc[i][1] + bb0.y;
        v0.z = acc[i][2] + bb0.z; v0.w = acc[i][3] + bb0.w;
        v1.x = acc[i][4] + bb1.x; v1.y = acc[i][5] + bb1.y;
        v1.z = acc[i][6] + bb1.z; v1.w = acc[i][7] + bb1.w;
        *(float4*)&g_h[(row0 + i) * GF + col0]     = v0;
        *(float4*)&g_h[(row0 + i) * GF + col0 + 4] = v1;
    }
}

// ---------------------------------------------------------------------------
// Kernel 2: repack g_h -> g_htf (tf32-rounded, mma-fragment order).
// Block (w = blockIdx.x 0..7, t = blockIdx.y 0..255) covers f in [w*64,+64),
// j in [t*32,+32). Output is one contiguous 8KB range per block.
// float4 index: ((t*8+w)*2+kp)*256 + nt*32 + lane ; component slot 0..3.
// element: f = w*64+nt*8+gid, j = t*32+kp*16+slot*4+tig (lane=gid*4+tig).
// ---------------------------------------------------------------------------
__global__ __launch_bounds__(256) void repack_kernel()
{
    __shared__ float sm[32][68];
    const int tid = threadIdx.x;
    const int w = blockIdx.x;
    const int t = blockIdx.y;

#pragma unroll
    for (int rep = 0; rep < 2; rep++) {
        const int idx = tid + rep * 256;
        const int j = idx >> 4, fq = idx & 15;
        float4 v = *(const float4*)&g_h[(size_t)(t * 32 + j) * GF + w * 64 + fq * 4];
        unsigned u;
        asm("cvt.rna.tf32.f32 %0, %1;" : "=r"(u) : "f"(v.x)); v.x = __uint_as_float(u);
        asm("cvt.rna.tf32.f32 %0, %1;" : "=r"(u) : "f"(v.y)); v.y = __uint_as_float(u);
        asm("cvt.rna.tf32.f32 %0, %1;" : "=r"(u) : "f"(v.z)); v.z = __uint_as_float(u);
        asm("cvt.rna.tf32.f32 %0, %1;" : "=r"(u) : "f"(v.w)); v.w = __uint_as_float(u);
        *(float4*)&sm[j][fq * 4] = v;
    }
    __syncthreads();

    float4* dst = (float4*)g_htf + (size_t)(t * 8 + w) * 512;
#pragma unroll
    for (int rep = 0; rep < 2; rep++) {
        const int o = tid + rep * 256;          // float4 index within block
        const int kp = o >> 8, r = o & 255;
        const int nt = r >> 5, lane = r & 31;
        const int gid = lane >> 2, tig = lane & 3;
        const int fl = nt * 8 + gid;
        float4 v;
        v.x = sm[kp * 16 + 0 * 4 + tig][fl];
        v.y = sm[kp * 16 + 1 * 4 + tig][fl];
        v.z = sm[kp * 16 + 2 * 4 + tig][fl];
        v.w = sm[kp * 16 + 3 * 4 + tig][fl];
        dst[o] = v;
    }
}

// ---------------------------------------------------------------------------
// Kernel 3: s1/s2 dots
// ---------------------------------------------------------------------------
__global__ __launch_bounds__(128) void s1s2_kernel(
    const float* __restrict__ a1, const float* __restrict__ a2)
{
    const int row = blockIdx.x;
    const int tid = threadIdx.x;

    float4 hv = *(const float4*)(g_h + row * GF + tid * 4);
    float4 v1 = *(const float4*)(a1 + tid * 4);
    float4 v2 = *(const float4*)(a2 + tid * 4);
    float p1 = hv.x * v1.x + hv.y * v1.y + hv.z * v1.z + hv.w * v1.w;
    float p2 = hv.x * v2.x + hv.y * v2.y + hv.z * v2.z + hv.w * v2.w;

#pragma unroll
    for (int o = 16; o > 0; o >>= 1) {
        p1 += __shfl_down_sync(0xffffffffu, p1, o);
        p2 += __shfl_down_sync(0xffffffffu, p2, o);
    }
    __shared__ float r1[4], r2[4];
    const int lane = tid & 31, w = tid >> 5;
    if (lane == 0) { r1[w] = p1; r2[w] = p2; }
    __syncthreads();
    if (tid == 0) {
        g_s1[row] = r1[0] + r1[1] + r1[2] + r1[3];
        g_s2[row] = r2[0] + r2[1] + r2[2] + r2[3];
    }
}

// ---------------------------------------------------------------------------
// Kernel 4: factorized exp precompute
// ---------------------------------------------------------------------------
__global__ __launch_bounds__(256) void prep_kernel(const float* __restrict__ b2p)
{
    const int i = blockIdx.x * 256 + threadIdx.x;
    const float b2 = *b2p;
    const float x1 = g_s1[i] + b2;
    const float x2 = g_s2[i];
    g_E1[i] = __expf(x1);
    g_F1[i] = __expf(0.2f * x1);
    g_E2[i] = __expf(x2);
    g_F2[i] = __expf(0.2f * x2);
}

// ---------------------------------------------------------------------------
// Kernel 5: fused attention. AM=32, AK=32, 256 threads, 2 CTA/SM.
// B operands: DIRECT LDG from fragment-packed g_htf (no smem for B at all).
// A operands: fragment-ready float4 via tiny smem PF (4KB). 2 barriers/tile.
// ---------------------------------------------------------------------------
#define AM 32
#define AK 32
#define NTT (GN / AK)                    // 256

__device__ __forceinline__ void mma8(float* c, float4 a, float b0, float b1)
{
    asm volatile(
        "mma.sync.aligned.m16n8k8.row.col.f32.tf32.tf32.f32 "
        "{%0,%1,%2,%3}, {%4,%5,%6,%7}, {%8,%9}, {%0,%1,%2,%3};\n"
        : "+f"(c[0]), "+f"(c[1]), "+f"(c[2]), "+f"(c[3])
        : "r"(__float_as_uint(a.x)), "r"(__float_as_uint(a.y)),
          "r"(__float_as_uint(a.z)), "r"(__float_as_uint(a.w)),
          "r"(__float_as_uint(b0)), "r"(__float_as_uint(b1)));
}

__device__ __forceinline__ float tf32r(float x)
{
    unsigned u;
    asm("cvt.rna.tf32.f32 %0, %1;" : "=r"(u) : "f"(x));
    return __uint_as_float(u);
}

__global__ __launch_bounds__(256, 2) void gat_attn4(
    const int* __restrict__ adj, float* __restrict__ out)
{
    __shared__ float4 PF[256];           // 8 A-frags x 32 lanes
    __shared__ float  ls[AM];

    const int tid  = threadIdx.x;
    const int w    = tid >> 5;           // warp 0..7 == producer frag id
    const int lane = tid & 31;
    const int gid  = lane >> 2;
    const int tig  = lane & 3;
    const int i0   = blockIdx.x * AM;

    if (tid < AM) ls[tid] = 0.f;

    // producer identity: frag f = w = ks*2+mt
    const int pks = w >> 1;
    const int pmt = w & 1;
    const int r0 = pmt * 16 + gid, r1 = r0 + 8;
    const int c0 = pks * 8 + tig,  c1 = c0 + 4;

    const float e1a = g_E1[i0 + r0], f1a = g_F1[i0 + r0];
    const float e1b = g_E1[i0 + r1], f1b = g_F1[i0 + r1];
    const int* arow0 = adj + (size_t)(i0 + r0) * GN;
    const int* arow1 = adj + (size_t)(i0 + r1) * GN;

    float lacc0 = 0.f, lacc1 = 0.f;
    float acc[2][8][4];
#pragma unroll
    for (int mt = 0; mt < 2; mt++)
#pragma unroll
        for (int nt = 0; nt < 8; nt++)
#pragma unroll
            for (int q = 0; q < 4; q++) acc[mt][nt][q] = 0.f;

    int a00, a01, a10, a11;
    float E2a, E2b, F2a, F2b;

#define PREF(J) do {                                                       \
    a00 = __ldg(arow0 + (J) + c0); a01 = __ldg(arow0 + (J) + c1);          \
    a10 = __ldg(arow1 + (J) + c0); a11 = __ldg(arow1 + (J) + c1);          \
    E2a = __ldg(&g_E2[(J) + c0]);  E2b = __ldg(&g_E2[(J) + c1]);           \
    F2a = __ldg(&g_F2[(J) + c0]);  F2b = __ldg(&g_F2[(J) + c1]);           \
} while (0)

    PREF(0);

    // B base: warp w reads float4 idx ((t*8+w)*2+kp)*256 + nt*32 + lane
    const float4* bwarp = (const float4*)g_htf + (size_t)w * 512 + lane;

    for (int t = 0; t < NTT; t++) {
        // ---- produce P fragments (factorized exp, zero MUFU)
        {
            float u00 = e1a * E2a, v00 = f1a * F2a;
            float u01 = e1a * E2b, v01 = f1a * F2b;
            float u10 = e1b * E2a, v10 = f1b * F2a;
            float u11 = e1b * E2b, v11 = f1b * F2b;
            float p00 = (a00 > 0) ? (u00 > 1.f ? u00 : v00) : 0.f;
            float p01 = (a01 > 0) ? (u01 > 1.f ? u01 : v01) : 0.f;
            float p10 = (a10 > 0) ? (u10 > 1.f ? u10 : v10) : 0.f;
            float p11 = (a11 > 0) ? (u11 > 1.f ? u11 : v11) : 0.f;
            p00 = tf32r(p00); p01 = tf32r(p01);
            p10 = tf32r(p10); p11 = tf32r(p11);
            lacc0 += p00 + p01; lacc1 += p10 + p11;
            PF[tid] = make_float4(p00, p10, p01, p11);
        }
        __syncthreads();                     // PF ready

        if (t + 1 < NTT) PREF((t + 1) * AK); // hide adj/EF latency under MMA

        const float4* bt = bwarp + (size_t)t * 4096;
#pragma unroll
        for (int kp = 0; kp < 2; kp++) {
            float4 bq[8];
#pragma unroll
            for (int nt = 0; nt < 8; nt++)
                bq[nt] = __ldg(bt + (size_t)kp * 256 + nt * 32);

            // A frags for ks = 2kp, 2kp+1 (frag f = ks*2+mt)
            const float4 afA0 = PF[(4 * kp + 0) * 32 + lane];
            const float4 afA1 = PF[(4 * kp + 1) * 32 + lane];
            const float4 afB0 = PF[(4 * kp + 2) * 32 + lane];
            const float4 afB1 = PF[(4 * kp + 3) * 32 + lane];

#pragma unroll
            for (int nt = 0; nt < 8; nt++) {
                mma8(acc[0][nt], afA0, bq[nt].x, bq[nt].y);
                mma8(acc[1][nt], afA1, bq[nt].x, bq[nt].y);
                mma8(acc[0][nt], afB0, bq[nt].z, bq[nt].w);
                mma8(acc[1][nt], afB1, bq[nt].z, bq[nt].w);
            }
        }
        __syncthreads();                     // PF consumed (WAR for t+1)
    }

    // ---- row sums: 16 threads contribute per row
    atomicAdd(&ls[r0], lacc0);
    atomicAdd(&ls[r1], lacc1);
    __syncthreads();

    // ---- epilogue: normalize + elu + store
#pragma unroll
    for (int mt = 0; mt < 2; mt++) {
        const int rA = mt * 16 + gid;
        const int rB = rA + 8;
        const float invA = 1.0f / ls[rA];
        const float invB = 1.0f / ls[rB];
#pragma unroll
        for (int nt = 0; nt < 8; nt++) {
            const int col = w * 64 + nt * 8 + tig * 2;
            float o0 = acc[mt][nt][0] * invA;
            float o1 = acc[mt][nt][1] * invA;
            float o2 = acc[mt][nt][2] * invB;
            float o3 = acc[mt][nt][3] * invB;
            o0 = o0 > 0.f ? o0 : (__expf(o0) - 1.f);
            o1 = o1 > 0.f ? o1 : (__expf(o1) - 1.f);
            o2 = o2 > 0.f ? o2 : (__expf(o2) - 1.f);
            o3 = o3 > 0.f ? o3 : (__expf(o3) - 1.f);
            *(float2*)&out[(size_t)(i0 + rA) * GF + col] = make_float2(o0, o1);
            *(float2*)&out[(size_t)(i0 + rB) * GF + col] = make_float2(o2, o3);
        }
    }
}

// ---------------------------------------------------------------------------
extern "C" void kernel_launch(void* const* d_in, const int* in_sizes, int n_in,
                              void* d_out, int out_size)
{
    const float* inp = (const float*)d_in[0];
    const int*   adj = (const int*)d_in[1];
    const float* W1  = (const float*)d_in[2];
    const float* b1  = (const float*)d_in[3];
    const float* a1  = (const float*)d_in[4];
    const float* a2  = (const float*)d_in[5];
    const float* b2  = (const float*)d_in[6];
    float* out = (float*)d_out;

    (void)in_sizes; (void)n_in; (void)out_size;

    gemm_h_kernel<<<dim3(GF / 128, GN / 128), 256>>>(inp, W1, b1);
    repack_kernel<<<dim3(8, 256), 256>>>();
    s1s2_kernel<<<GN, 128>>>(a1, a2);
    prep_kernel<<<GN / 256, 256>>>(b2);
    gat_attn4<<<GN / AM, 256>>>(adj, out);
}